// round 3
// baseline (speedup 1.0000x reference)
#include <cuda_runtime.h>
#include <cstdio>
#include <math.h>

// ---------------------------------------------------------------------------
// Retention: out[b,i,:] = sum_{j<=i} alpha^(i-j)/16 * (q_i . k_j) * v_j
// q,k,v from qkv = x @ Wqkv + bqkv   (x:[8,4096,256], Wqkv:[256,768])
// Chunked linear-attention formulation, fp32 with packed f32x2 FMAs.
// ---------------------------------------------------------------------------

#define BB    8
#define LL    4096
#define DD    256
#define CC    128
#define TT    (LL / CC)      // 32 chunks
#define NQKV  768
#define MTOT  (BB * LL)      // 32768
#define ALPHAF 0.99f

typedef unsigned long long u64t;

// ---- f32x2 helpers ---------------------------------------------------------
__device__ __forceinline__ u64t pk2(float a, float b) {
    u64t r; asm("mov.b64 %0, {%1,%2};" : "=l"(r) : "f"(a), "f"(b)); return r;
}
__device__ __forceinline__ void up2(u64t v, float& a, float& b) {
    asm("mov.b64 {%0,%1}, %2;" : "=f"(a), "=f"(b) : "l"(v));
}
__device__ __forceinline__ u64t ffma2(u64t a, u64t b, u64t c) {
    u64t d; asm("fma.rn.f32x2 %0, %1, %2, %3;" : "=l"(d) : "l"(a), "l"(b), "l"(c)); return d;
}
__device__ __forceinline__ u64t fmul2(u64t a, u64t b) {
    u64t d; asm("mul.rn.f32x2 %0, %1, %2;" : "=l"(d) : "l"(a), "l"(b)); return d;
}

// ---- scratch (device globals; no runtime allocation) -----------------------
__device__ float g_q[MTOT * DD];                 // 33.5 MB
__device__ float g_k[MTOT * DD];
__device__ float g_v[MTOT * DD];
__device__ float g_A[BB * TT * CC * CC];         // 16.8 MB decayed intra scores

// ===========================================================================
// Kernel 1: QKV projection.  y = x @ W + b, split into g_q / g_k / g_v.
// Tile 128x128, 256 threads, 8x8 per thread (f32x2 pairs on the N axis).
// ===========================================================================
__global__ void k_proj(const float* __restrict__ x,
                       const float* __restrict__ W,
                       const float* __restrict__ bias) {
    __shared__ __align__(16) float Xs[32 * 132];   // [kk][row], pad 132
    __shared__ __align__(16) float Wsm[32 * 132];  // [kk][col], pad 132

    const int tid = threadIdx.x;
    const int ty = tid >> 4, tx = tid & 15;
    const int m0 = blockIdx.x * 128;
    const int n0 = blockIdx.y * 128;

    u64t acc[8][4] = {};

    for (int kt = 0; kt < 8; ++kt) {
        __syncthreads();
        // stage X tile [128 rows][32 k], transposed into Xs[kk][row]
        for (int idx = tid; idx < 4096; idx += 256) {
            int kk = idx & 31, mm = idx >> 5;
            Xs[kk * 132 + mm] = x[(size_t)(m0 + mm) * DD + kt * 32 + kk];
        }
        // stage W tile [32 k][128 n]
        for (int idx = tid; idx < 4096; idx += 256) {
            int nn = idx & 127, kk = idx >> 7;
            Wsm[kk * 132 + nn] = W[(size_t)(kt * 32 + kk) * NQKV + n0 + nn];
        }
        __syncthreads();

        #pragma unroll
        for (int kk = 0; kk < 32; ++kk) {
            const float4 a0 = *(const float4*)(Xs + kk * 132 + ty * 8);
            const float4 a1 = *(const float4*)(Xs + kk * 132 + ty * 8 + 4);
            const u64t* wp = (const u64t*)(Wsm + kk * 132 + tx * 8);
            const u64t w0 = wp[0], w1 = wp[1], w2 = wp[2], w3 = wp[3];
            float av[8] = {a0.x, a0.y, a0.z, a0.w, a1.x, a1.y, a1.z, a1.w};
            #pragma unroll
            for (int i = 0; i < 8; ++i) {
                u64t aa = pk2(av[i], av[i]);
                acc[i][0] = ffma2(aa, w0, acc[i][0]);
                acc[i][1] = ffma2(aa, w1, acc[i][1]);
                acc[i][2] = ffma2(aa, w2, acc[i][2]);
                acc[i][3] = ffma2(aa, w3, acc[i][3]);
            }
        }
    }

    // epilogue: add bias, route to q/k/v (128-wide n-tiles never straddle 256)
    const int cg0 = n0 + tx * 8;
    const int which = cg0 >> 8;
    float* dst = (which == 0) ? g_q : (which == 1 ? g_k : g_v);
    const int off = cg0 & 255;
    float bv[8];
    #pragma unroll
    for (int u = 0; u < 8; ++u) bv[u] = bias[cg0 + u];

    #pragma unroll
    for (int i = 0; i < 8; ++i) {
        size_t mg = (size_t)(m0 + ty * 8 + i);
        float o[8];
        up2(acc[i][0], o[0], o[1]); up2(acc[i][1], o[2], o[3]);
        up2(acc[i][2], o[4], o[5]); up2(acc[i][3], o[6], o[7]);
        float4 r0 = make_float4(o[0] + bv[0], o[1] + bv[1], o[2] + bv[2], o[3] + bv[3]);
        float4 r1 = make_float4(o[4] + bv[4], o[5] + bv[5], o[6] + bv[6], o[7] + bv[7]);
        *(float4*)(dst + mg * DD + off) = r0;
        *(float4*)(dst + mg * DD + off + 4) = r1;
    }
}

// ===========================================================================
// Kernel 2: intra-chunk decayed scores.
// A[b,t,r,p] = (p<=r) ? alpha^(r-p)/16 * (q_{tC+r} . k_{tC+p}) : 0
// One CTA per (b, t). 128x128 output, 8x8 per thread, K=256 in 8 tiles.
// ===========================================================================
__global__ void k_scores() {
    __shared__ __align__(16) float Qs[32 * 132];   // [kk][row]
    __shared__ __align__(16) float Ks[32 * 132];   // [kk][col]
    __shared__ float tabB[128];

    const int tid = threadIdx.x;
    const int ty = tid >> 4, tx = tid & 15;
    const int bi = blockIdx.x >> 5;
    const int t  = blockIdx.x & 31;
    const size_t rowbase = ((size_t)bi * LL + (size_t)t * CC);

    if (tid < 128) tabB[tid] = powf(ALPHAF, (float)tid) * 0.0625f;

    u64t acc[8][4] = {};

    for (int kt = 0; kt < 8; ++kt) {
        __syncthreads();
        for (int idx = tid; idx < 4096; idx += 256) {
            int kk = idx & 31, rr = idx >> 5;
            Qs[kk * 132 + rr] = g_q[(rowbase + rr) * DD + kt * 32 + kk];
        }
        for (int idx = tid; idx < 4096; idx += 256) {
            int kk = idx & 31, rr = idx >> 5;
            Ks[kk * 132 + rr] = g_k[(rowbase + rr) * DD + kt * 32 + kk];
        }
        __syncthreads();

        #pragma unroll
        for (int kk = 0; kk < 32; ++kk) {
            const float4 a0 = *(const float4*)(Qs + kk * 132 + ty * 8);
            const float4 a1 = *(const float4*)(Qs + kk * 132 + ty * 8 + 4);
            const u64t* wp = (const u64t*)(Ks + kk * 132 + tx * 8);
            const u64t w0 = wp[0], w1 = wp[1], w2 = wp[2], w3 = wp[3];
            float av[8] = {a0.x, a0.y, a0.z, a0.w, a1.x, a1.y, a1.z, a1.w};
            #pragma unroll
            for (int i = 0; i < 8; ++i) {
                u64t aa = pk2(av[i], av[i]);
                acc[i][0] = ffma2(aa, w0, acc[i][0]);
                acc[i][1] = ffma2(aa, w1, acc[i][1]);
                acc[i][2] = ffma2(aa, w2, acc[i][2]);
                acc[i][3] = ffma2(aa, w3, acc[i][3]);
            }
        }
    }

    float* Adst = g_A + (((size_t)bi * TT + t) << 14);
    #pragma unroll
    for (int i = 0; i < 8; ++i) {
        const int rr = ty * 8 + i;
        float o[8];
        up2(acc[i][0], o[0], o[1]); up2(acc[i][1], o[2], o[3]);
        up2(acc[i][2], o[4], o[5]); up2(acc[i][3], o[6], o[7]);
        #pragma unroll
        for (int u = 0; u < 8; ++u) {
            int pp = tx * 8 + u;
            o[u] = (pp <= rr) ? o[u] * tabB[rr - pp] : 0.0f;
        }
        *(float4*)(Adst + (size_t)rr * CC + tx * 8)     = make_float4(o[0], o[1], o[2], o[3]);
        *(float4*)(Adst + (size_t)rr * CC + tx * 8 + 4) = make_float4(o[4], o[5], o[6], o[7]);
    }
}

// ===========================================================================
// Kernel 3: sequential chunk scan.
// Grid = 8 batches x 16 column-slices (16 v-columns each) = 128 CTAs (1 wave).
// Per chunk: out = A@V + alpha^(r+1)/16 * q@S ; S = alpha^C*S + sum a^(C-1-r) k v^T
// State S[256][16] lives in smem; f32x2 pairs along the n axis everywhere.
// ===========================================================================
#define SCAN_SMEM_BYTES ((16512 + 16512) * 4 + (2304 + 1024) * 8 + 512)

__global__ void k_scan(float* __restrict__ out) {
    extern __shared__ __align__(16) char smraw[];
    float* As   = (float*)smraw;            // [128][129] intra scores
    float* Qm   = As + 16512;               // [128 mm][129] q tile (m-major)
    u64t*  Ss   = (u64t*)(Qm + 16512);      // [256][9]  state rows (8 u64 + pad)
    u64t*  Vs   = Ss + 2304;                // [128][8]  v slice rows
    float* tabA = (float*)(Vs + 1024);      // alpha^(127-r)

    const int tid = threadIdx.x;
    const int b  = blockIdx.x >> 4;
    const int n0 = (blockIdx.x & 15) << 4;
    const int r = tid & 127, h = tid >> 7;

    for (int i = tid; i < 2304; i += 256) Ss[i] = 0ULL;
    if (tid < 128) tabA[tid] = powf(ALPHAF, (float)(127 - tid));

    const float drv = powf(ALPHAF, (float)(r + 1)) * 0.0625f;
    const u64t dr2 = pk2(drv, drv);
    const float aC = powf(ALPHAF, 128.0f);
    const u64t aC2 = pk2(aC, aC);

    for (int t = 0; t < TT; ++t) {
        __syncthreads();
        // ---- stage A chunk (padded rows of 129) and V slice ----
        const float4* A4 = (const float4*)(g_A + (((size_t)b * TT + t) << 14));
        for (int i4 = tid; i4 < 4096; i4 += 256) {
            float4 v = A4[i4];
            int row = i4 >> 5, c4 = i4 & 31;
            float* d = As + row * 129 + (c4 << 2);
            d[0] = v.x; d[1] = v.y; d[2] = v.z; d[3] = v.w;
        }
        {
            const float* vsrc = g_v + (((size_t)b * LL + (size_t)t * CC) << 8) + n0;
            float* Vf = (float*)Vs;
            for (int idx = tid; idx < 2048; idx += 256) {
                int row = idx >> 4, n = idx & 15;
                Vf[(row << 4) + n] = vsrc[((size_t)row << 8) + n];
            }
        }
        __syncthreads();

        // ---- phase a: intra  out[r,n] = sum_j A[r,j] V[j,n] ----
        u64t accO[4] = {0ULL, 0ULL, 0ULL, 0ULL};
        {
            const float* Ar = As + r * 129;
            const u64t* Vh = Vs + (h << 2);
            #pragma unroll 8
            for (int j = 0; j < 128; ++j) {
                float a = Ar[j];
                u64t aa = pk2(a, a);
                const u64t* vj = Vh + (j << 3);
                accO[0] = ffma2(aa, vj[0], accO[0]);
                accO[1] = ffma2(aa, vj[1], accO[1]);
                accO[2] = ffma2(aa, vj[2], accO[2]);
                accO[3] = ffma2(aa, vj[3], accO[3]);
            }
        }

        // ---- phase b: inter  accI[r,n] = sum_m q[r,m] S[m,n] (two m-tiles) --
        u64t accI[4] = {0ULL, 0ULL, 0ULL, 0ULL};
        for (int mt = 0; mt < 2; ++mt) {
            __syncthreads();
            const float* qsrc = g_q + (((size_t)b * LL + (size_t)t * CC) << 8) + (mt << 7);
            for (int idx = tid; idx < 16384; idx += 256) {
                int mm = idx & 127, rr2 = idx >> 7;
                Qm[mm * 129 + rr2] = qsrc[((size_t)rr2 << 8) + mm];
            }
            __syncthreads();
            const u64t* Sb = Ss + ((mt << 7) * 9) + (h << 2);
            #pragma unroll 8
            for (int mm = 0; mm < 128; ++mm) {
                float qv = Qm[mm * 129 + r];
                u64t qq = pk2(qv, qv);
                const u64t* Sr = Sb + mm * 9;
                accI[0] = ffma2(qq, Sr[0], accI[0]);
                accI[1] = ffma2(qq, Sr[1], accI[1]);
                accI[2] = ffma2(qq, Sr[2], accI[2]);
                accI[3] = ffma2(qq, Sr[3], accI[3]);
            }
        }

        // ---- combine & store ----
        {
            float* op = out + (((size_t)b * LL + (size_t)t * CC + r) << 8) + n0 + (h << 3);
            u64t c0 = ffma2(dr2, accI[0], accO[0]);
            u64t c1 = ffma2(dr2, accI[1], accO[1]);
            u64t c2 = ffma2(dr2, accI[2], accO[2]);
            u64t c3 = ffma2(dr2, accI[3], accO[3]);
            float o0, o1, o2, o3, o4, o5, o6, o7;
            up2(c0, o0, o1); up2(c1, o2, o3); up2(c2, o4, o5); up2(c3, o6, o7);
            *(float4*)op       = make_float4(o0, o1, o2, o3);
            *(float4*)(op + 4) = make_float4(o4, o5, o6, o7);
        }

        // ---- phase c: state update (thread = m row of S) ----
        __syncthreads();
        {
            const int m = tid;
            u64t* Sm = Ss + m * 9;
            u64t s[8];
            #pragma unroll
            for (int i = 0; i < 8; ++i) s[i] = fmul2(aC2, Sm[i]);
            const float* kp = g_k + (((size_t)b * LL + (size_t)t * CC) << 8) + m;
            #pragma unroll 4
            for (int r2 = 0; r2 < 128; ++r2) {
                float kv = kp[(size_t)r2 << 8] * tabA[r2];
                u64t kk2 = pk2(kv, kv);
                const u64t* vr = Vs + (r2 << 3);
                #pragma unroll
                for (int i = 0; i < 8; ++i) s[i] = ffma2(kk2, vr[i], s[i]);
            }
            #pragma unroll
            for (int i = 0; i < 8; ++i) Sm[i] = s[i];
        }
    }
}

// ===========================================================================
extern "C" void kernel_launch(void* const* d_in, const int* in_sizes, int n_in,
                              void* d_out, int out_size) {
    const float* x    = (const float*)d_in[0];   // [8,4096,256]
    const float* W    = (const float*)d_in[1];   // [256,768]
    const float* bias = (const float*)d_in[2];   // [768]
    float* out = (float*)d_out;                  // [8,4096,256]

    (void)in_sizes; (void)n_in; (void)out_size;

    cudaFuncSetAttribute(k_scan, cudaFuncAttributeMaxDynamicSharedMemorySize,
                         SCAN_SMEM_BYTES);

    k_proj<<<dim3(MTOT / 128, NQKV / 128, 1), 256>>>(x, W, bias);
    k_scores<<<BB * TT, 256>>>();
    k_scan<<<BB * 16, 256, SCAN_SMEM_BYTES>>>(out);
}

// round 7
// speedup vs baseline: 2.0820x; 2.0820x over previous
#include <cuda_runtime.h>
#include <math.h>

// ---------------------------------------------------------------------------
// Retention: out[b,i,:] = sum_{j<=i} alpha^(i-j)/16 * (q_i . k_j) * v_j
// Fully parallel chunked formulation:
//   intra: out = (tril(alpha^{r-p}) * qk^T/16) @ V           (per chunk GEMMs)
//   G_t[m,n] = sum_r alpha^(127-r) k[r,m] v[r,n]             (per chunk GEMMs)
//   S_t = alpha^128 * S_{t-1} + G_{t-1}                      (elementwise scan)
//   inter: out += alpha^(r+1)/16 * q @ S_t                   (per chunk GEMMs)
// fp32 with packed f32x2 FMAs throughout.
// ---------------------------------------------------------------------------

#define BB    8
#define LL    4096
#define DD    256
#define CC    128
#define TT    (LL / CC)      // 32 chunks
#define NQKV  768
#define MTOT  (BB * LL)      // 32768
#define ALPHAF 0.99f

typedef unsigned long long u64t;

// ---- f32x2 helpers ---------------------------------------------------------
__device__ __forceinline__ u64t pk2(float a, float b) {
    u64t r; asm("mov.b64 %0, {%1,%2};" : "=l"(r) : "f"(a), "f"(b)); return r;
}
__device__ __forceinline__ void up2(u64t v, float& a, float& b) {
    asm("mov.b64 {%0,%1}, %2;" : "=f"(a), "=f"(b) : "l"(v));
}
__device__ __forceinline__ u64t ffma2(u64t a, u64t b, u64t c) {
    u64t d; asm("fma.rn.f32x2 %0, %1, %2, %3;" : "=l"(d) : "l"(a), "l"(b), "l"(c)); return d;
}

// ---- scratch (device globals; no runtime allocation) -----------------------
__device__ float g_q[MTOT * DD];                 // 33.5 MB
__device__ float g_k[MTOT * DD];
__device__ float g_v[MTOT * DD];
__device__ float g_G[BB * TT * DD * DD];         // 67 MB: G chunks, then S in-place

// ===========================================================================
// Kernel 1: QKV projection.  y = x @ W + b, split into g_q / g_k / g_v.
// ===========================================================================
__global__ void k_proj(const float* __restrict__ x,
                       const float* __restrict__ W,
                       const float* __restrict__ bias) {
    __shared__ __align__(16) float Xs[32 * 132];   // [kk][row]
    __shared__ __align__(16) float Wsm[32 * 132];  // [kk][col]

    const int tid = threadIdx.x;
    const int ty = tid >> 4, tx = tid & 15;
    const int m0 = blockIdx.x * 128;
    const int n0 = blockIdx.y * 128;

    u64t acc[8][4] = {};

    for (int kt = 0; kt < 8; ++kt) {
        __syncthreads();
        for (int idx = tid; idx < 4096; idx += 256) {
            int kk = idx & 31, mm = idx >> 5;
            Xs[kk * 132 + mm] = x[(size_t)(m0 + mm) * DD + kt * 32 + kk];
        }
        for (int idx = tid; idx < 4096; idx += 256) {
            int nn = idx & 127, kk = idx >> 7;
            Wsm[kk * 132 + nn] = W[(size_t)(kt * 32 + kk) * NQKV + n0 + nn];
        }
        __syncthreads();

        #pragma unroll
        for (int kk = 0; kk < 32; ++kk) {
            const float4 a0 = *(const float4*)(Xs + kk * 132 + ty * 8);
            const float4 a1 = *(const float4*)(Xs + kk * 132 + ty * 8 + 4);
            const u64t* wp = (const u64t*)(Wsm + kk * 132 + tx * 8);
            const u64t w0 = wp[0], w1 = wp[1], w2 = wp[2], w3 = wp[3];
            float av[8] = {a0.x, a0.y, a0.z, a0.w, a1.x, a1.y, a1.z, a1.w};
            #pragma unroll
            for (int i = 0; i < 8; ++i) {
                u64t aa = pk2(av[i], av[i]);
                acc[i][0] = ffma2(aa, w0, acc[i][0]);
                acc[i][1] = ffma2(aa, w1, acc[i][1]);
                acc[i][2] = ffma2(aa, w2, acc[i][2]);
                acc[i][3] = ffma2(aa, w3, acc[i][3]);
            }
        }
    }

    const int cg0 = n0 + tx * 8;
    const int which = cg0 >> 8;
    float* dst = (which == 0) ? g_q : (which == 1 ? g_k : g_v);
    const int off = cg0 & 255;
    float bv[8];
    #pragma unroll
    for (int u = 0; u < 8; ++u) bv[u] = bias[cg0 + u];

    #pragma unroll
    for (int i = 0; i < 8; ++i) {
        size_t mg = (size_t)(m0 + ty * 8 + i);
        float o[8];
        up2(acc[i][0], o[0], o[1]); up2(acc[i][1], o[2], o[3]);
        up2(acc[i][2], o[4], o[5]); up2(acc[i][3], o[6], o[7]);
        *(float4*)(dst + mg * DD + off) =
            make_float4(o[0] + bv[0], o[1] + bv[1], o[2] + bv[2], o[3] + bv[3]);
        *(float4*)(dst + mg * DD + off + 4) =
            make_float4(o[4] + bv[4], o[5] + bv[5], o[6] + bv[6], o[7] + bv[7]);
    }
}

// ===========================================================================
// Kernel 2: fused intra-chunk: A = tril-decayed q k^T / 16 (in smem), then
// out = A @ V written straight to global out.  One CTA per (b,t).
// Dyn smem: As 128x132 | {phase1: Qs 32x132 + Ks 32x132 | phase2: Vt 128x132}
// ===========================================================================
#define SC2_SMEM ((128 * 132 + 128 * 132) * 4)

__global__ void k_scores2(float* __restrict__ out) {
    extern __shared__ __align__(16) float smf[];
    float* As = smf;                 // [128][132]
    float* Qs = As + 128 * 132;      // [32][132]
    float* Ks = Qs + 32 * 132;       // [32][132]
    float* Vt = As + 128 * 132;      // [128][132]  (aliases Qs/Ks)
    __shared__ float tabB[128];

    const int tid = threadIdx.x;
    const int ty = tid >> 4, tx = tid & 15;
    const int bi = blockIdx.x >> 5;
    const int t  = blockIdx.x & 31;
    const size_t rowbase = (size_t)bi * LL + (size_t)t * CC;

    if (tid < 128) tabB[tid] = powf(ALPHAF, (float)tid) * 0.0625f;

    u64t acc[8][4] = {};

    // ---- phase 1: scores ----
    for (int kt = 0; kt < 8; ++kt) {
        __syncthreads();
        for (int idx = tid; idx < 4096; idx += 256) {
            int kk = idx & 31, rr = idx >> 5;
            Qs[kk * 132 + rr] = g_q[(rowbase + rr) * DD + kt * 32 + kk];
        }
        for (int idx = tid; idx < 4096; idx += 256) {
            int kk = idx & 31, rr = idx >> 5;
            Ks[kk * 132 + rr] = g_k[(rowbase + rr) * DD + kt * 32 + kk];
        }
        __syncthreads();

        #pragma unroll
        for (int kk = 0; kk < 32; ++kk) {
            const float4 a0 = *(const float4*)(Qs + kk * 132 + ty * 8);
            const float4 a1 = *(const float4*)(Qs + kk * 132 + ty * 8 + 4);
            const u64t* wp = (const u64t*)(Ks + kk * 132 + tx * 8);
            const u64t w0 = wp[0], w1 = wp[1], w2 = wp[2], w3 = wp[3];
            float av[8] = {a0.x, a0.y, a0.z, a0.w, a1.x, a1.y, a1.z, a1.w};
            #pragma unroll
            for (int i = 0; i < 8; ++i) {
                u64t aa = pk2(av[i], av[i]);
                acc[i][0] = ffma2(aa, w0, acc[i][0]);
                acc[i][1] = ffma2(aa, w1, acc[i][1]);
                acc[i][2] = ffma2(aa, w2, acc[i][2]);
                acc[i][3] = ffma2(aa, w3, acc[i][3]);
            }
        }
    }

    // decay + mask, park A in smem
    #pragma unroll
    for (int i = 0; i < 8; ++i) {
        const int rr = ty * 8 + i;
        float o[8];
        up2(acc[i][0], o[0], o[1]); up2(acc[i][1], o[2], o[3]);
        up2(acc[i][2], o[4], o[5]); up2(acc[i][3], o[6], o[7]);
        #pragma unroll
        for (int u = 0; u < 8; ++u) {
            int pp = tx * 8 + u;
            o[u] = (pp <= rr) ? o[u] * tabB[rr - pp] : 0.0f;
        }
        *(float4*)(As + rr * 132 + tx * 8)     = make_float4(o[0], o[1], o[2], o[3]);
        *(float4*)(As + rr * 132 + tx * 8 + 4) = make_float4(o[4], o[5], o[6], o[7]);
    }

    // ---- phase 2: out = A @ V, two n-halves of 128 ----
    for (int nh = 0; nh < 2; ++nh) {
        __syncthreads();   // covers As writes (first pass) and Vt reuse (second)
        for (int i4 = tid; i4 < 4096; i4 += 256) {
            int n4 = i4 & 31, j = i4 >> 5;
            *(float4*)(Vt + j * 132 + n4 * 4) =
                *(const float4*)(g_v + (rowbase + j) * DD + nh * 128 + n4 * 4);
        }
        __syncthreads();

        u64t acc2[8][4] = {};
        #pragma unroll 4
        for (int j4 = 0; j4 < 32; ++j4) {
            float av[8][4];
            #pragma unroll
            for (int i = 0; i < 8; ++i)
                *(float4*)av[i] = *(const float4*)(As + (ty * 8 + i) * 132 + j4 * 4);
            #pragma unroll
            for (int jj = 0; jj < 4; ++jj) {
                const u64t* vp = (const u64t*)(Vt + (j4 * 4 + jj) * 132 + tx * 8);
                const u64t w0 = vp[0], w1 = vp[1], w2 = vp[2], w3 = vp[3];
                #pragma unroll
                for (int i = 0; i < 8; ++i) {
                    u64t aa = pk2(av[i][jj], av[i][jj]);
                    acc2[i][0] = ffma2(aa, w0, acc2[i][0]);
                    acc2[i][1] = ffma2(aa, w1, acc2[i][1]);
                    acc2[i][2] = ffma2(aa, w2, acc2[i][2]);
                    acc2[i][3] = ffma2(aa, w3, acc2[i][3]);
                }
            }
        }

        #pragma unroll
        for (int i = 0; i < 8; ++i) {
            float o[8];
            up2(acc2[i][0], o[0], o[1]); up2(acc2[i][1], o[2], o[3]);
            up2(acc2[i][2], o[4], o[5]); up2(acc2[i][3], o[6], o[7]);
            float* op = out + (rowbase + ty * 8 + i) * DD + nh * 128 + tx * 8;
            *(float4*)op       = make_float4(o[0], o[1], o[2], o[3]);
            *(float4*)(op + 4) = make_float4(o[4], o[5], o[6], o[7]);
        }
    }
}

// ===========================================================================
// Kernel 3: chunk summaries  G[b,t][m,n] = sum_r alpha^(127-r) k[r,m] v[r,n]
// Grid: (b,t) x 4 quadrants of 128x128; K = 128 over r in 4 tiles of 32.
// ===========================================================================
__global__ void k_G() {
    __shared__ __align__(16) float Kd[32 * 132];
    __shared__ __align__(16) float Vs[32 * 132];
    __shared__ float tabA[128];

    const int tid = threadIdx.x;
    const int ty = tid >> 4, tx = tid & 15;
    const int bt = blockIdx.x >> 2;
    const int quad = blockIdx.x & 3;
    const int mi = quad >> 1, ni = quad & 1;
    const int b = bt >> 5, t = bt & 31;
    const size_t rowbase = (size_t)b * LL + (size_t)t * CC;

    if (tid < 128) tabA[tid] = powf(ALPHAF, (float)(127 - tid));
    __syncthreads();

    u64t acc[8][4] = {};

    for (int rt = 0; rt < 4; ++rt) {
        __syncthreads();
        // stage 32 rows x 128 floats = 1024 float4s  (BUGFIX: was 2048)
        for (int i4 = tid; i4 < 1024; i4 += 256) {
            int m4 = i4 & 31, rr = i4 >> 5;     // rr in [0,32)
            float sc = tabA[rt * 32 + rr];
            float4 kv = *(const float4*)(g_k + (rowbase + rt * 32 + rr) * DD + mi * 128 + m4 * 4);
            *(float4*)(Kd + rr * 132 + m4 * 4) =
                make_float4(kv.x * sc, kv.y * sc, kv.z * sc, kv.w * sc);
            *(float4*)(Vs + rr * 132 + m4 * 4) =
                *(const float4*)(g_v + (rowbase + rt * 32 + rr) * DD + ni * 128 + m4 * 4);
        }
        __syncthreads();

        #pragma unroll
        for (int kk = 0; kk < 32; ++kk) {
            const float4 a0 = *(const float4*)(Kd + kk * 132 + ty * 8);
            const float4 a1 = *(const float4*)(Kd + kk * 132 + ty * 8 + 4);
            const u64t* wp = (const u64t*)(Vs + kk * 132 + tx * 8);
            const u64t w0 = wp[0], w1 = wp[1], w2 = wp[2], w3 = wp[3];
            float av[8] = {a0.x, a0.y, a0.z, a0.w, a1.x, a1.y, a1.z, a1.w};
            #pragma unroll
            for (int i = 0; i < 8; ++i) {
                u64t aa = pk2(av[i], av[i]);
                acc[i][0] = ffma2(aa, w0, acc[i][0]);
                acc[i][1] = ffma2(aa, w1, acc[i][1]);
                acc[i][2] = ffma2(aa, w2, acc[i][2]);
                acc[i][3] = ffma2(aa, w3, acc[i][3]);
            }
        }
    }

    float* Gd = g_G + ((size_t)bt << 16);
    #pragma unroll
    for (int i = 0; i < 8; ++i) {
        float o[8];
        up2(acc[i][0], o[0], o[1]); up2(acc[i][1], o[2], o[3]);
        up2(acc[i][2], o[4], o[5]); up2(acc[i][3], o[6], o[7]);
        float* gp = Gd + (size_t)(mi * 128 + ty * 8 + i) * DD + ni * 128 + tx * 8;
        *(float4*)gp       = make_float4(o[0], o[1], o[2], o[3]);
        *(float4*)(gp + 4) = make_float4(o[4], o[5], o[6], o[7]);
    }
}

// ===========================================================================
// Kernel 4: elementwise prefix scan (in place): S_t = a^128 * S_{t-1} + G_{t-1}
// g_G[t] is overwritten with S_t.  131072 threads, float4 each, 32 steps.
// ===========================================================================
__global__ void k_prefix() {
    const int id = blockIdx.x * 256 + threadIdx.x;       // 0..131071
    const int b = id >> 14;
    const int e4 = id & 16383;
    float4* p = (float4*)g_G + ((size_t)b * 32) * 16384 + e4;
    const float a128 = powf(ALPHAF, 128.0f);
    float4 s = make_float4(0.f, 0.f, 0.f, 0.f);
    #pragma unroll 4
    for (int t = 0; t < TT; ++t) {
        float4 g = p[(size_t)t * 16384];
        p[(size_t)t * 16384] = s;
        s.x = a128 * s.x + g.x; s.y = a128 * s.y + g.y;
        s.z = a128 * s.z + g.z; s.w = a128 * s.w + g.w;
    }
}

// ===========================================================================
// Kernel 5: inter-chunk: out += alpha^(r+1)/16 * q @ S_t
// Grid: (b,t) x 2 n-halves; output 128x128, K = 256 in 8 tiles of 32.
// ===========================================================================
__global__ void k_inter(float* __restrict__ out) {
    const int bt = blockIdx.x >> 1;
    const int nh = blockIdx.x & 1;
    const int b = bt >> 5, t = bt & 31;
    if (t == 0) return;                       // S_0 = 0

    __shared__ __align__(16) float Qs[32 * 132];
    __shared__ __align__(16) float Ss[32 * 132];

    const int tid = threadIdx.x;
    const int ty = tid >> 4, tx = tid & 15;
    const size_t rowbase = (size_t)b * LL + (size_t)t * CC;
    const float* Sbase = g_G + ((size_t)bt << 16);

    u64t acc[8][4] = {};

    for (int kt = 0; kt < 8; ++kt) {
        __syncthreads();
        for (int idx = tid; idx < 4096; idx += 256) {
            int kk = idx & 31, rr = idx >> 5;
            Qs[kk * 132 + rr] = g_q[(rowbase + rr) * DD + kt * 32 + kk];
        }
        for (int i4 = tid; i4 < 1024; i4 += 256) {
            int n4 = i4 & 31, kk = i4 >> 5;
            *(float4*)(Ss + kk * 132 + n4 * 4) =
                *(const float4*)(Sbase + (size_t)(kt * 32 + kk) * DD + nh * 128 + n4 * 4);
        }
        __syncthreads();

        #pragma unroll
        for (int kk = 0; kk < 32; ++kk) {
            const float4 a0 = *(const float4*)(Qs + kk * 132 + ty * 8);
            const float4 a1 = *(const float4*)(Qs + kk * 132 + ty * 8 + 4);
            const u64t* wp = (const u64t*)(Ss + kk * 132 + tx * 8);
            const u64t w0 = wp[0], w1 = wp[1], w2 = wp[2], w3 = wp[3];
            float av[8] = {a0.x, a0.y, a0.z, a0.w, a1.x, a1.y, a1.z, a1.w};
            #pragma unroll
            for (int i = 0; i < 8; ++i) {
                u64t aa = pk2(av[i], av[i]);
                acc[i][0] = ffma2(aa, w0, acc[i][0]);
                acc[i][1] = ffma2(aa, w1, acc[i][1]);
                acc[i][2] = ffma2(aa, w2, acc[i][2]);
                acc[i][3] = ffma2(aa, w3, acc[i][3]);
            }
        }
    }

    #pragma unroll
    for (int i = 0; i < 8; ++i) {
        const int rr = ty * 8 + i;
        const float sc = powf(ALPHAF, (float)(rr + 1)) * 0.0625f;
        float o[8];
        up2(acc[i][0], o[0], o[1]); up2(acc[i][1], o[2], o[3]);
        up2(acc[i][2], o[4], o[5]); up2(acc[i][3], o[6], o[7]);
        float* op = out + (rowbase + rr) * DD + nh * 128 + tx * 8;
        float4 c0 = *(const float4*)op;
        float4 c1 = *(const float4*)(op + 4);
        *(float4*)op = make_float4(c0.x + sc * o[0], c0.y + sc * o[1],
                                   c0.z + sc * o[2], c0.w + sc * o[3]);
        *(float4*)(op + 4) = make_float4(c1.x + sc * o[4], c1.y + sc * o[5],
                                         c1.z + sc * o[6], c1.w + sc * o[7]);
    }
}

// ===========================================================================
extern "C" void kernel_launch(void* const* d_in, const int* in_sizes, int n_in,
                              void* d_out, int out_size) {
    const float* x    = (const float*)d_in[0];   // [8,4096,256]
    const float* W    = (const float*)d_in[1];   // [256,768]
    const float* bias = (const float*)d_in[2];   // [768]
    float* out = (float*)d_out;                  // [8,4096,256]

    (void)in_sizes; (void)n_in; (void)out_size;

    cudaFuncSetAttribute(k_scores2, cudaFuncAttributeMaxDynamicSharedMemorySize,
                         SC2_SMEM);

    k_proj<<<dim3(MTOT / 128, NQKV / 128, 1), 256>>>(x, W, bias);
    k_scores2<<<BB * TT, 256, SC2_SMEM>>>(out);
    k_G<<<BB * TT * 4, 256>>>();
    k_prefix<<<512, 256>>>();
    k_inter<<<BB * TT * 2, 256>>>(out);
}

// round 13
// speedup vs baseline: 2.0827x; 1.0003x over previous
#include <cuda_runtime.h>
#include <math.h>

// ---------------------------------------------------------------------------
// Retention, fully parallel chunked formulation (all FFMA2 / f32x2):
//   intra: out = (tril(alpha^{r-p}) * qk^T/16) @ V           (per chunk GEMMs)
//   G_t[m,n] = sum_r alpha^(127-r) k[r,m] v[r,n]             (per chunk GEMMs)
//   S_t = alpha^128 * S_{t-1} + G_{t-1}                      (elementwise scan)
//   inter: out += alpha^(r+1)/16 * q @ S_t                   (per chunk GEMMs)
// Broadcast operands are stored DUPLICATED in smem so the f32x2 multiplier
// pair comes straight out of LDS (no MOV-packing in the inner loop).
// ---------------------------------------------------------------------------

#define BB    8
#define LL    4096
#define DD    256
#define CC    128
#define TT    (LL / CC)
#define NQKV  768
#define MTOT  (BB * LL)
#define ALPHAF 0.99f
#define DSTR  268            // duplicated-row stride in floats (1072 B, 16B-aligned)

typedef unsigned long long u64t;

__device__ __forceinline__ void up2(u64t v, float& a, float& b) {
    asm("mov.b64 {%0,%1}, %2;" : "=f"(a), "=f"(b) : "l"(v));
}
__device__ __forceinline__ u64t ffma2(u64t a, u64t b, u64t c) {
    u64t d; asm("fma.rn.f32x2 %0, %1, %2, %3;" : "=l"(d) : "l"(a), "l"(b), "l"(c)); return d;
}

// ---- scratch (device globals; no runtime allocation) -----------------------
__device__ float g_q[MTOT * DD];
__device__ float g_k[MTOT * DD];
__device__ float g_v[MTOT * DD];
__device__ float g_G[BB * TT * DD * DD];   // G chunks, then S in-place

// 8x8 f32x2 microkernel step: 8 A pairs (duplicated, contiguous) x 8 B floats
#define MK_STEP(Abase, Bbase)                                                  \
    do {                                                                       \
        const ulonglong2* ap = (const ulonglong2*)(Abase);                     \
        const ulonglong2 p0 = ap[0], p1 = ap[1], p2 = ap[2], p3 = ap[3];       \
        const ulonglong2* bp = (const ulonglong2*)(Bbase);                     \
        const ulonglong2 q0 = bp[0], q1 = bp[1];                               \
        const u64t w0 = q0.x, w1 = q0.y, w2 = q1.x, w3 = q1.y;                 \
        u64t av[8] = {p0.x, p0.y, p1.x, p1.y, p2.x, p2.y, p3.x, p3.y};         \
        _Pragma("unroll")                                                      \
        for (int i = 0; i < 8; ++i) {                                          \
            acc[i][0] = ffma2(av[i], w0, acc[i][0]);                           \
            acc[i][1] = ffma2(av[i], w1, acc[i][1]);                           \
            acc[i][2] = ffma2(av[i], w2, acc[i][2]);                           \
            acc[i][3] = ffma2(av[i], w3, acc[i][3]);                           \
        }                                                                      \
    } while (0)

// ===========================================================================
// Kernel 1: QKV projection.  y = x @ W + b, split into g_q / g_k / g_v.
// ===========================================================================
__global__ void __launch_bounds__(256, 2)
k_proj(const float* __restrict__ x,
       const float* __restrict__ W,
       const float* __restrict__ bias) {
    __shared__ __align__(16) float Xs2[32 * DSTR];   // [kk][2*row] duplicated
    __shared__ __align__(16) float Wsm[32 * 132];    // [kk][col]

    const int tid = threadIdx.x;
    const int ty = tid >> 4, tx = tid & 15;
    const int m0 = blockIdx.x * 128;
    const int n0 = blockIdx.y * 128;

    u64t acc[8][4] = {};

    for (int kt = 0; kt < 8; ++kt) {
        __syncthreads();
        for (int idx = tid; idx < 4096; idx += 256) {
            int kk = idx & 31, mm = idx >> 5;
            float v = x[(size_t)(m0 + mm) * DD + kt * 32 + kk];
            *(float2*)(Xs2 + kk * DSTR + 2 * mm) = make_float2(v, v);
        }
        for (int idx = tid; idx < 4096; idx += 256) {
            int nn = idx & 127, kk = idx >> 7;
            Wsm[kk * 132 + nn] = W[(size_t)(kt * 32 + kk) * NQKV + n0 + nn];
        }
        __syncthreads();

        #pragma unroll
        for (int kk = 0; kk < 32; ++kk)
            MK_STEP(Xs2 + kk * DSTR + ty * 16, Wsm + kk * 132 + tx * 8);
    }

    const int cg0 = n0 + tx * 8;
    const int which = cg0 >> 8;
    float* dst = (which == 0) ? g_q : (which == 1 ? g_k : g_v);
    const int off = cg0 & 255;
    float bv[8];
    #pragma unroll
    for (int u = 0; u < 8; ++u) bv[u] = bias[cg0 + u];

    #pragma unroll
    for (int i = 0; i < 8; ++i) {
        size_t mg = (size_t)(m0 + ty * 8 + i);
        float o[8];
        up2(acc[i][0], o[0], o[1]); up2(acc[i][1], o[2], o[3]);
        up2(acc[i][2], o[4], o[5]); up2(acc[i][3], o[6], o[7]);
        *(float4*)(dst + mg * DD + off) =
            make_float4(o[0] + bv[0], o[1] + bv[1], o[2] + bv[2], o[3] + bv[3]);
        *(float4*)(dst + mg * DD + off + 4) =
            make_float4(o[4] + bv[4], o[5] + bv[5], o[6] + bv[6], o[7] + bv[7]);
    }
}

// ===========================================================================
// Kernel 2: fused intra-chunk: A = tril-decayed q k^T / 16 (duplicated smem),
// then out = A @ V straight to global.  One CTA per (b,t).
// smem: As2 [128][DSTR] | { Qs2 [32][DSTR] + Ks [32][132]  |  Vt [128][132] }
// ===========================================================================
#define SC2_SMEM ((128 * DSTR + 128 * 132) * 4)

__global__ void k_scores2(float* __restrict__ out) {
    extern __shared__ __align__(16) float smf[];
    float* As2 = smf;                   // [128][DSTR] duplicated
    float* Vt  = As2 + 128 * DSTR;      // [128][132]
    float* Qs2 = Vt;                    // [32][DSTR] duplicated (aliases Vt)
    float* Ks  = Qs2 + 32 * DSTR;       // [32][132]
    __shared__ float tabB[128];

    const int tid = threadIdx.x;
    const int ty = tid >> 4, tx = tid & 15;
    const int bi = blockIdx.x >> 5;
    const int t  = blockIdx.x & 31;
    const size_t rowbase = (size_t)bi * LL + (size_t)t * CC;

    if (tid < 128) tabB[tid] = powf(ALPHAF, (float)tid) * 0.0625f;

    {
        u64t acc[8][4] = {};

        // ---- phase 1: scores ----
        for (int kt = 0; kt < 8; ++kt) {
            __syncthreads();
            for (int idx = tid; idx < 4096; idx += 256) {
                int kk = idx & 31, rr = idx >> 5;
                float v = g_q[(rowbase + rr) * DD + kt * 32 + kk];
                *(float2*)(Qs2 + kk * DSTR + 2 * rr) = make_float2(v, v);
            }
            for (int idx = tid; idx < 4096; idx += 256) {
                int kk = idx & 31, rr = idx >> 5;
                Ks[kk * 132 + rr] = g_k[(rowbase + rr) * DD + kt * 32 + kk];
            }
            __syncthreads();

            #pragma unroll
            for (int kk = 0; kk < 32; ++kk)
                MK_STEP(Qs2 + kk * DSTR + ty * 16, Ks + kk * 132 + tx * 8);
        }

        // decay + mask, park A (duplicated) in smem
        #pragma unroll
        for (int i = 0; i < 8; ++i) {
            const int rr = ty * 8 + i;
            float o[8];
            up2(acc[i][0], o[0], o[1]); up2(acc[i][1], o[2], o[3]);
            up2(acc[i][2], o[4], o[5]); up2(acc[i][3], o[6], o[7]);
            #pragma unroll
            for (int u = 0; u < 8; ++u) {
                int pp = tx * 8 + u;
                o[u] = (pp <= rr) ? o[u] * tabB[rr - pp] : 0.0f;
            }
            float* ad = As2 + rr * DSTR + 2 * (tx * 8);
            *(float4*)(ad)      = make_float4(o[0], o[0], o[1], o[1]);
            *(float4*)(ad + 4)  = make_float4(o[2], o[2], o[3], o[3]);
            *(float4*)(ad + 8)  = make_float4(o[4], o[4], o[5], o[5]);
            *(float4*)(ad + 12) = make_float4(o[6], o[6], o[7], o[7]);
        }
    }

    // ---- phase 2: out = A @ V, two n-halves of 128 ----
    for (int nh = 0; nh < 2; ++nh) {
        __syncthreads();   // covers As2 writes (first pass) and Vt reuse
        for (int i4 = tid; i4 < 4096; i4 += 256) {
            int n4 = i4 & 31, j = i4 >> 5;
            *(float4*)(Vt + j * 132 + n4 * 4) =
                *(const float4*)(g_v + (rowbase + j) * DD + nh * 128 + n4 * 4);
        }
        __syncthreads();

        u64t acc[8][4] = {};
        #pragma unroll 4
        for (int j = 0; j < 128; ++j) {
            const ulonglong2* bp = (const ulonglong2*)(Vt + j * 132 + tx * 8);
            const ulonglong2 q0 = bp[0], q1 = bp[1];
            const u64t w0 = q0.x, w1 = q0.y, w2 = q1.x, w3 = q1.y;
            #pragma unroll
            for (int i = 0; i < 8; ++i) {
                const u64t aa = *(const u64t*)(As2 + (ty * 8 + i) * DSTR + 2 * j);
                acc[i][0] = ffma2(aa, w0, acc[i][0]);
                acc[i][1] = ffma2(aa, w1, acc[i][1]);
                acc[i][2] = ffma2(aa, w2, acc[i][2]);
                acc[i][3] = ffma2(aa, w3, acc[i][3]);
            }
        }

        #pragma unroll
        for (int i = 0; i < 8; ++i) {
            float o[8];
            up2(acc[i][0], o[0], o[1]); up2(acc[i][1], o[2], o[3]);
            up2(acc[i][2], o[4], o[5]); up2(acc[i][3], o[6], o[7]);
            float* op = out + (rowbase + ty * 8 + i) * DD + nh * 128 + tx * 8;
            *(float4*)op       = make_float4(o[0], o[1], o[2], o[3]);
            *(float4*)(op + 4) = make_float4(o[4], o[5], o[6], o[7]);
        }
    }
}

// ===========================================================================
// Kernel 3: chunk summaries  G[b,t][m,n] = sum_r alpha^(127-r) k[r,m] v[r,n]
// ===========================================================================
__global__ void __launch_bounds__(256, 2) k_G() {
    __shared__ __align__(16) float Kd2[32 * DSTR];   // [rr][2*m] duplicated, pre-scaled
    __shared__ __align__(16) float Vs[32 * 132];
    __shared__ float tabA[128];

    const int tid = threadIdx.x;
    const int ty = tid >> 4, tx = tid & 15;
    const int bt = blockIdx.x >> 2;
    const int quad = blockIdx.x & 3;
    const int mi = quad >> 1, ni = quad & 1;
    const int b = bt >> 5, t = bt & 31;
    const size_t rowbase = (size_t)b * LL + (size_t)t * CC;

    if (tid < 128) tabA[tid] = powf(ALPHAF, (float)(127 - tid));
    __syncthreads();

    u64t acc[8][4] = {};

    for (int rt = 0; rt < 4; ++rt) {
        __syncthreads();
        for (int i4 = tid; i4 < 1024; i4 += 256) {
            int m4 = i4 & 31, rr = i4 >> 5;
            float sc = tabA[rt * 32 + rr];
            float4 kv = *(const float4*)(g_k + (rowbase + rt * 32 + rr) * DD + mi * 128 + m4 * 4);
            float* kd = Kd2 + rr * DSTR + m4 * 8;
            *(float4*)(kd)     = make_float4(kv.x * sc, kv.x * sc, kv.y * sc, kv.y * sc);
            *(float4*)(kd + 4) = make_float4(kv.z * sc, kv.z * sc, kv.w * sc, kv.w * sc);
            *(float4*)(Vs + rr * 132 + m4 * 4) =
                *(const float4*)(g_v + (rowbase + rt * 32 + rr) * DD + ni * 128 + m4 * 4);
        }
        __syncthreads();

        #pragma unroll
        for (int kk = 0; kk < 32; ++kk)
            MK_STEP(Kd2 + kk * DSTR + ty * 16, Vs + kk * 132 + tx * 8);
    }

    float* Gd = g_G + ((size_t)bt << 16);
    #pragma unroll
    for (int i = 0; i < 8; ++i) {
        float o[8];
        up2(acc[i][0], o[0], o[1]); up2(acc[i][1], o[2], o[3]);
        up2(acc[i][2], o[4], o[5]); up2(acc[i][3], o[6], o[7]);
        float* gp = Gd + (size_t)(mi * 128 + ty * 8 + i) * DD + ni * 128 + tx * 8;
        *(float4*)gp       = make_float4(o[0], o[1], o[2], o[3]);
        *(float4*)(gp + 4) = make_float4(o[4], o[5], o[6], o[7]);
    }
}

// ===========================================================================
// Kernel 4: elementwise prefix scan with next-chunk prefetch (MLP 2).
// ===========================================================================
__global__ void k_prefix() {
    const int id = blockIdx.x * 256 + threadIdx.x;
    const int b = id >> 14;
    const int e4 = id & 16383;
    float4* p = (float4*)g_G + ((size_t)b * 32) * 16384 + e4;
    const float a128 = powf(ALPHAF, 128.0f);
    float4 s = make_float4(0.f, 0.f, 0.f, 0.f);
    float4 g = p[0];
    #pragma unroll
    for (int t = 0; t < TT; ++t) {
        float4 gn = make_float4(0.f, 0.f, 0.f, 0.f);
        if (t + 1 < TT) gn = p[(size_t)(t + 1) * 16384];
        p[(size_t)t * 16384] = s;
        s.x = fmaf(a128, s.x, g.x); s.y = fmaf(a128, s.y, g.y);
        s.z = fmaf(a128, s.z, g.z); s.w = fmaf(a128, s.w, g.w);
        g = gn;
    }
}

// ===========================================================================
// Kernel 5: inter-chunk: out += alpha^(r+1)/16 * q @ S_t
// ===========================================================================
__global__ void __launch_bounds__(256, 2) k_inter(float* __restrict__ out) {
    const int bt = blockIdx.x >> 1;
    const int nh = blockIdx.x & 1;
    const int b = bt >> 5, t = bt & 31;
    if (t == 0) return;

    __shared__ __align__(16) float Qs2[32 * DSTR];   // duplicated
    __shared__ __align__(16) float Ss[32 * 132];

    const int tid = threadIdx.x;
    const int ty = tid >> 4, tx = tid & 15;
    const size_t rowbase = (size_t)b * LL + (size_t)t * CC;
    const float* Sbase = g_G + ((size_t)bt << 16);

    u64t acc[8][4] = {};

    for (int kt = 0; kt < 8; ++kt) {
        __syncthreads();
        for (int idx = tid; idx < 4096; idx += 256) {
            int kk = idx & 31, rr = idx >> 5;
            float v = g_q[(rowbase + rr) * DD + kt * 32 + kk];
            *(float2*)(Qs2 + kk * DSTR + 2 * rr) = make_float2(v, v);
        }
        for (int i4 = tid; i4 < 1024; i4 += 256) {
            int n4 = i4 & 31, kk = i4 >> 5;
            *(float4*)(Ss + kk * 132 + n4 * 4) =
                *(const float4*)(Sbase + (size_t)(kt * 32 + kk) * DD + nh * 128 + n4 * 4);
        }
        __syncthreads();

        #pragma unroll
        for (int kk = 0; kk < 32; ++kk)
            MK_STEP(Qs2 + kk * DSTR + ty * 16, Ss + kk * 132 + tx * 8);
    }

    #pragma unroll
    for (int i = 0; i < 8; ++i) {
        const int rr = ty * 8 + i;
        const float sc = powf(ALPHAF, (float)(rr + 1)) * 0.0625f;
        float o[8];
        up2(acc[i][0], o[0], o[1]); up2(acc[i][1], o[2], o[3]);
        up2(acc[i][2], o[4], o[5]); up2(acc[i][3], o[6], o[7]);
        float* op = out + (rowbase + rr) * DD + nh * 128 + tx * 8;
        float4 c0 = *(const float4*)op;
        float4 c1 = *(const float4*)(op + 4);
        *(float4*)op = make_float4(c0.x + sc * o[0], c0.y + sc * o[1],
                                   c0.z + sc * o[2], c0.w + sc * o[3]);
        *(float4*)(op + 4) = make_float4(c1.x + sc * o[4], c1.y + sc * o[5],
                                         c1.z + sc * o[6], c1.w + sc * o[7]);
    }
}

// ===========================================================================
extern "C" void kernel_launch(void* const* d_in, const int* in_sizes, int n_in,
                              void* d_out, int out_size) {
    const float* x    = (const float*)d_in[0];
    const float* W    = (const float*)d_in[1];
    const float* bias = (const float*)d_in[2];
    float* out = (float*)d_out;

    (void)in_sizes; (void)n_in; (void)out_size;

    cudaFuncSetAttribute(k_scores2, cudaFuncAttributeMaxDynamicSharedMemorySize,
                         SC2_SMEM);

    k_proj<<<dim3(MTOT / 128, NQKV / 128, 1), 256>>>(x, W, bias);
    k_scores2<<<BB * TT, 256, SC2_SMEM>>>(out);
    k_G<<<BB * TT * 4, 256>>>();
    k_prefix<<<512, 256>>>();
    k_inter<<<BB * TT * 2, 256>>>(out);
}

// round 14
// speedup vs baseline: 2.6978x; 1.2954x over previous
#include <cuda_runtime.h>
#include <math.h>

// ---------------------------------------------------------------------------
// Retention, fully parallel chunked formulation (all FFMA2 / f32x2):
//   intra: out = (tril(alpha^{r-p}) * qk^T/16) @ V           (per chunk GEMMs)
//   G_t[m,n] = sum_r alpha^(127-r) k[r,m] v[r,n]             (per chunk GEMMs)
//   S_t = alpha^128 * S_{t-1} + G_{t-1}                      (elementwise scan)
//   inter: out += alpha^(r+1)/16 * q @ S_t                   (per chunk GEMMs)
// All GEMM kernels use register-prefetch double buffering: the next k-tile's
// global loads are issued into registers before the current tile's FFMA block,
// hiding global latency under compute. Shared memory stays single-buffered.
// ---------------------------------------------------------------------------

#define BB    8
#define LL    4096
#define DD    256
#define CC    128
#define TT    (LL / CC)
#define NQKV  768
#define MTOT  (BB * LL)
#define ALPHAF 0.99f

typedef unsigned long long u64t;

__device__ __forceinline__ u64t pk2(float a, float b) {
    u64t r; asm("mov.b64 %0, {%1,%2};" : "=l"(r) : "f"(a), "f"(b)); return r;
}
__device__ __forceinline__ void up2(u64t v, float& a, float& b) {
    asm("mov.b64 {%0,%1}, %2;" : "=f"(a), "=f"(b) : "l"(v));
}
__device__ __forceinline__ u64t ffma2(u64t a, u64t b, u64t c) {
    u64t d; asm("fma.rn.f32x2 %0, %1, %2, %3;" : "=l"(d) : "l"(a), "l"(b), "l"(c)); return d;
}

// ---- scratch (device globals; no runtime allocation) -----------------------
__device__ float g_q[MTOT * DD];
__device__ float g_k[MTOT * DD];
__device__ float g_v[MTOT * DD];
__device__ float g_G[BB * TT * DD * DD];   // G chunks, then S in-place

// 8x8 f32x2 microkernel step (R7-proven): A broadcast via pk2, B as pairs.
#define MK_STEP(Abase, Bbase)                                                  \
    do {                                                                       \
        const float4 a0 = *(const float4*)(Abase);                             \
        const float4 a1 = *(const float4*)((Abase) + 4);                       \
        const u64t* wp = (const u64t*)(Bbase);                                 \
        const u64t w0 = wp[0], w1 = wp[1], w2 = wp[2], w3 = wp[3];             \
        float av[8] = {a0.x, a0.y, a0.z, a0.w, a1.x, a1.y, a1.z, a1.w};        \
        _Pragma("unroll")                                                      \
        for (int i = 0; i < 8; ++i) {                                          \
            u64t aa = pk2(av[i], av[i]);                                       \
            acc[i][0] = ffma2(aa, w0, acc[i][0]);                              \
            acc[i][1] = ffma2(aa, w1, acc[i][1]);                              \
            acc[i][2] = ffma2(aa, w2, acc[i][2]);                              \
            acc[i][3] = ffma2(aa, w3, acc[i][3]);                              \
        }                                                                      \
    } while (0)

// ===========================================================================
// Kernel 1: QKV projection.  y = x @ W + b, split into g_q / g_k / g_v.
// Register-prefetched staging: rx/rw hold k-tile kt+1 while kt computes.
// ===========================================================================
__global__ void __launch_bounds__(256, 2)
k_proj(const float* __restrict__ x,
       const float* __restrict__ W,
       const float* __restrict__ bias) {
    __shared__ __align__(16) float Xs[32 * 132];   // [kk][row]
    __shared__ __align__(16) float Wsm[32 * 132];  // [kk][col]

    const int tid = threadIdx.x;
    const int ty = tid >> 4, tx = tid & 15;
    const int m0 = blockIdx.x * 128;
    const int n0 = blockIdx.y * 128;

    float rx[16], rw[16];
    #pragma unroll
    for (int it = 0; it < 16; ++it) {
        int idx = tid + it * 256;
        rx[it] = x[(size_t)(m0 + (idx >> 5)) * DD + (idx & 31)];
        rw[it] = W[(size_t)(idx >> 7) * NQKV + n0 + (idx & 127)];
    }

    u64t acc[8][4] = {};

    for (int kt = 0; kt < 8; ++kt) {
        __syncthreads();
        #pragma unroll
        for (int it = 0; it < 16; ++it) {
            int idx = tid + it * 256;
            Xs[(idx & 31) * 132 + (idx >> 5)] = rx[it];
            Wsm[(idx >> 7) * 132 + (idx & 127)] = rw[it];
        }
        __syncthreads();

        if (kt < 7) {
            #pragma unroll
            for (int it = 0; it < 16; ++it) {
                int idx = tid + it * 256;
                rx[it] = x[(size_t)(m0 + (idx >> 5)) * DD + (kt + 1) * 32 + (idx & 31)];
                rw[it] = W[(size_t)((kt + 1) * 32 + (idx >> 7)) * NQKV + n0 + (idx & 127)];
            }
        }

        #pragma unroll
        for (int kk = 0; kk < 32; ++kk)
            MK_STEP(Xs + kk * 132 + ty * 8, Wsm + kk * 132 + tx * 8);
    }

    const int cg0 = n0 + tx * 8;
    const int which = cg0 >> 8;
    float* dst = (which == 0) ? g_q : (which == 1 ? g_k : g_v);
    const int off = cg0 & 255;
    float bv[8];
    #pragma unroll
    for (int u = 0; u < 8; ++u) bv[u] = bias[cg0 + u];

    #pragma unroll
    for (int i = 0; i < 8; ++i) {
        size_t mg = (size_t)(m0 + ty * 8 + i);
        float o[8];
        up2(acc[i][0], o[0], o[1]); up2(acc[i][1], o[2], o[3]);
        up2(acc[i][2], o[4], o[5]); up2(acc[i][3], o[6], o[7]);
        *(float4*)(dst + mg * DD + off) =
            make_float4(o[0] + bv[0], o[1] + bv[1], o[2] + bv[2], o[3] + bv[3]);
        *(float4*)(dst + mg * DD + off + 4) =
            make_float4(o[4] + bv[4], o[5] + bv[5], o[6] + bv[6], o[7] + bv[7]);
    }
}

// ===========================================================================
// Kernel 2: fused intra-chunk.  A = tril-decayed q k^T / 16 parked in smem,
// then out = A @ V with V streamed in 32-row tiles (reg-prefetched).
// smem: As[128][132] + stage{ Qs[32][132]+Ks[32][132] | Vt[32][132] }
//   = (16896 + 8448) * 4 = 101376 B  ->  2 CTAs/SM, single wave of 256 CTAs.
// ===========================================================================
#define SC2_SMEM ((128 * 132 + 2 * 32 * 132) * 4)

__global__ void __launch_bounds__(256, 2) k_scores2(float* __restrict__ out) {
    extern __shared__ __align__(16) float smf[];
    float* As = smf;                  // [128][132]
    float* Qs = As + 128 * 132;       // [32][132]
    float* Ks = Qs + 32 * 132;        // [32][132]
    float* Vt = Qs;                   // [32][132] (aliases Qs in phase 2)
    __shared__ float tabB[128];

    const int tid = threadIdx.x;
    const int ty = tid >> 4, tx = tid & 15;
    const int bi = blockIdx.x >> 5;
    const int t  = blockIdx.x & 31;
    const size_t rowbase = (size_t)bi * LL + (size_t)t * CC;

    if (tid < 128) tabB[tid] = powf(ALPHAF, (float)tid) * 0.0625f;

    // ---- phase 1: scores, reg-prefetched ----
    {
        float rq[16], rk[16];
        #pragma unroll
        for (int it = 0; it < 16; ++it) {
            int idx = tid + it * 256;
            int kk = idx & 31, rr = idx >> 5;
            rq[it] = g_q[(rowbase + rr) * DD + kk];
            rk[it] = g_k[(rowbase + rr) * DD + kk];
        }

        u64t acc[8][4] = {};

        for (int kt = 0; kt < 8; ++kt) {
            __syncthreads();
            #pragma unroll
            for (int it = 0; it < 16; ++it) {
                int idx = tid + it * 256;
                int kk = idx & 31, rr = idx >> 5;
                Qs[kk * 132 + rr] = rq[it];
                Ks[kk * 132 + rr] = rk[it];
            }
            __syncthreads();

            if (kt < 7) {
                #pragma unroll
                for (int it = 0; it < 16; ++it) {
                    int idx = tid + it * 256;
                    int kk = idx & 31, rr = idx >> 5;
                    rq[it] = g_q[(rowbase + rr) * DD + (kt + 1) * 32 + kk];
                    rk[it] = g_k[(rowbase + rr) * DD + (kt + 1) * 32 + kk];
                }
            }

            #pragma unroll
            for (int kk = 0; kk < 32; ++kk)
                MK_STEP(Qs + kk * 132 + ty * 8, Ks + kk * 132 + tx * 8);
        }

        // decay + mask, park A in smem (no sync needed before write: each
        // thread writes only its own output tile region; sync comes in phase 2)
        #pragma unroll
        for (int i = 0; i < 8; ++i) {
            const int rr = ty * 8 + i;
            float o[8];
            up2(acc[i][0], o[0], o[1]); up2(acc[i][1], o[2], o[3]);
            up2(acc[i][2], o[4], o[5]); up2(acc[i][3], o[6], o[7]);
            #pragma unroll
            for (int u = 0; u < 8; ++u) {
                int pp = tx * 8 + u;
                o[u] = (pp <= rr) ? o[u] * tabB[rr - pp] : 0.0f;
            }
            *(float4*)(As + rr * 132 + tx * 8)     = make_float4(o[0], o[1], o[2], o[3]);
            *(float4*)(As + rr * 132 + tx * 8 + 4) = make_float4(o[4], o[5], o[6], o[7]);
        }
    }

    // ---- phase 2: out = A @ V; V streamed as 8 tiles of 32 rows ----
    {
        float rv[16];
        // prefetch tile s=0  (nh=0, jt=0)
        #pragma unroll
        for (int it = 0; it < 16; ++it) {
            int idx = tid + it * 256;
            rv[it] = g_v[(rowbase + (idx >> 7)) * DD + (idx & 127)];
        }

        for (int nh = 0; nh < 2; ++nh) {
            u64t acc[8][4] = {};
            for (int jt = 0; jt < 4; ++jt) {
                const int s = nh * 4 + jt;
                __syncthreads();   // covers As writes (s=0) / prior tile reads
                #pragma unroll
                for (int it = 0; it < 16; ++it) {
                    int idx = tid + it * 256;
                    Vt[(idx >> 7) * 132 + (idx & 127)] = rv[it];
                }
                __syncthreads();

                if (s < 7) {
                    const int nh2 = (s + 1) >> 2, jt2 = (s + 1) & 3;
                    #pragma unroll
                    for (int it = 0; it < 16; ++it) {
                        int idx = tid + it * 256;
                        rv[it] = g_v[(rowbase + jt2 * 32 + (idx >> 7)) * DD
                                     + nh2 * 128 + (idx & 127)];
                    }
                }

                #pragma unroll
                for (int j4 = 0; j4 < 8; ++j4) {
                    float av[8][4];
                    #pragma unroll
                    for (int i = 0; i < 8; ++i)
                        *(float4*)av[i] =
                            *(const float4*)(As + (ty * 8 + i) * 132 + jt * 32 + j4 * 4);
                    #pragma unroll
                    for (int jj = 0; jj < 4; ++jj) {
                        const u64t* vp = (const u64t*)(Vt + (j4 * 4 + jj) * 132 + tx * 8);
                        const u64t w0 = vp[0], w1 = vp[1], w2 = vp[2], w3 = vp[3];
                        #pragma unroll
                        for (int i = 0; i < 8; ++i) {
                            u64t aa = pk2(av[i][jj], av[i][jj]);
                            acc[i][0] = ffma2(aa, w0, acc[i][0]);
                            acc[i][1] = ffma2(aa, w1, acc[i][1]);
                            acc[i][2] = ffma2(aa, w2, acc[i][2]);
                            acc[i][3] = ffma2(aa, w3, acc[i][3]);
                        }
                    }
                }
            }

            #pragma unroll
            for (int i = 0; i < 8; ++i) {
                float o[8];
                up2(acc[i][0], o[0], o[1]); up2(acc[i][1], o[2], o[3]);
                up2(acc[i][2], o[4], o[5]); up2(acc[i][3], o[6], o[7]);
                float* op = out + (rowbase + ty * 8 + i) * DD + nh * 128 + tx * 8;
                *(float4*)op       = make_float4(o[0], o[1], o[2], o[3]);
                *(float4*)(op + 4) = make_float4(o[4], o[5], o[6], o[7]);
            }
        }
    }
}

// ===========================================================================
// Kernel 3: chunk summaries  G[b,t][m,n] = sum_r alpha^(127-r) k[r,m] v[r,n]
// Reg-prefetched float4 staging (scale applied at STS time).
// ===========================================================================
__global__ void __launch_bounds__(256, 2) k_G() {
    __shared__ __align__(16) float Kd[32 * 132];
    __shared__ __align__(16) float Vs[32 * 132];
    __shared__ float tabA[128];

    const int tid = threadIdx.x;
    const int ty = tid >> 4, tx = tid & 15;
    const int bt = blockIdx.x >> 2;
    const int quad = blockIdx.x & 3;
    const int mi = quad >> 1, ni = quad & 1;
    const int b = bt >> 5, t = bt & 31;
    const size_t rowbase = (size_t)b * LL + (size_t)t * CC;

    if (tid < 128) tabA[tid] = powf(ALPHAF, (float)(127 - tid));
    __syncthreads();

    float4 rk4[4], rv4[4];
    #pragma unroll
    for (int it = 0; it < 4; ++it) {
        int i4 = tid + it * 256;
        int m4 = i4 & 31, rr = i4 >> 5;
        rk4[it] = *(const float4*)(g_k + (rowbase + rr) * DD + mi * 128 + m4 * 4);
        rv4[it] = *(const float4*)(g_v + (rowbase + rr) * DD + ni * 128 + m4 * 4);
    }

    u64t acc[8][4] = {};

    for (int rt = 0; rt < 4; ++rt) {
        __syncthreads();
        #pragma unroll
        for (int it = 0; it < 4; ++it) {
            int i4 = tid + it * 256;
            int m4 = i4 & 31, rr = i4 >> 5;
            float sc = tabA[rt * 32 + rr];
            *(float4*)(Kd + rr * 132 + m4 * 4) =
                make_float4(rk4[it].x * sc, rk4[it].y * sc, rk4[it].z * sc, rk4[it].w * sc);
            *(float4*)(Vs + rr * 132 + m4 * 4) = rv4[it];
        }
        __syncthreads();

        if (rt < 3) {
            #pragma unroll
            for (int it = 0; it < 4; ++it) {
                int i4 = tid + it * 256;
                int m4 = i4 & 31, rr = i4 >> 5;
                rk4[it] = *(const float4*)(g_k + (rowbase + (rt + 1) * 32 + rr) * DD
                                           + mi * 128 + m4 * 4);
                rv4[it] = *(const float4*)(g_v + (rowbase + (rt + 1) * 32 + rr) * DD
                                           + ni * 128 + m4 * 4);
            }
        }

        #pragma unroll
        for (int kk = 0; kk < 32; ++kk)
            MK_STEP(Kd + kk * 132 + ty * 8, Vs + kk * 132 + tx * 8);
    }

    float* Gd = g_G + ((size_t)bt << 16);
    #pragma unroll
    for (int i = 0; i < 8; ++i) {
        float o[8];
        up2(acc[i][0], o[0], o[1]); up2(acc[i][1], o[2], o[3]);
        up2(acc[i][2], o[4], o[5]); up2(acc[i][3], o[6], o[7]);
        float* gp = Gd + (size_t)(mi * 128 + ty * 8 + i) * DD + ni * 128 + tx * 8;
        *(float4*)gp       = make_float4(o[0], o[1], o[2], o[3]);
        *(float4*)(gp + 4) = make_float4(o[4], o[5], o[6], o[7]);
    }
}

// ===========================================================================
// Kernel 4: elementwise prefix scan with next-chunk prefetch (MLP 2).
// ===========================================================================
__global__ void k_prefix() {
    const int id = blockIdx.x * 256 + threadIdx.x;
    const int b = id >> 14;
    const int e4 = id & 16383;
    float4* p = (float4*)g_G + ((size_t)b * 32) * 16384 + e4;
    const float a128 = powf(ALPHAF, 128.0f);
    float4 s = make_float4(0.f, 0.f, 0.f, 0.f);
    float4 g = p[0];
    #pragma unroll
    for (int t = 0; t < TT; ++t) {
        float4 gn = make_float4(0.f, 0.f, 0.f, 0.f);
        if (t + 1 < TT) gn = p[(size_t)(t + 1) * 16384];
        p[(size_t)t * 16384] = s;
        s.x = fmaf(a128, s.x, g.x); s.y = fmaf(a128, s.y, g.y);
        s.z = fmaf(a128, s.z, g.z); s.w = fmaf(a128, s.w, g.w);
        g = gn;
    }
}

// ===========================================================================
// Kernel 5: inter-chunk: out += alpha^(r+1)/16 * q @ S_t   (reg-prefetched)
// ===========================================================================
__global__ void __launch_bounds__(256, 2) k_inter(float* __restrict__ out) {
    const int bt = blockIdx.x >> 1;
    const int nh = blockIdx.x & 1;
    const int b = bt >> 5, t = bt & 31;
    if (t == 0) return;

    __shared__ __align__(16) float Qs[32 * 132];
    __shared__ __align__(16) float Ss[32 * 132];

    const int tid = threadIdx.x;
    const int ty = tid >> 4, tx = tid & 15;
    const size_t rowbase = (size_t)b * LL + (size_t)t * CC;
    const float* Sbase = g_G + ((size_t)bt << 16);

    float rq[16];
    float4 rs4[4];
    #pragma unroll
    for (int it = 0; it < 16; ++it) {
        int idx = tid + it * 256;
        rq[it] = g_q[(rowbase + (idx >> 5)) * DD + (idx & 31)];
    }
    #pragma unroll
    for (int it = 0; it < 4; ++it) {
        int i4 = tid + it * 256;
        rs4[it] = *(const float4*)(Sbase + (size_t)(i4 >> 5) * DD + nh * 128 + (i4 & 31) * 4);
    }

    u64t acc[8][4] = {};

    for (int kt = 0; kt < 8; ++kt) {
        __syncthreads();
        #pragma unroll
        for (int it = 0; it < 16; ++it) {
            int idx = tid + it * 256;
            Qs[(idx & 31) * 132 + (idx >> 5)] = rq[it];
        }
        #pragma unroll
        for (int it = 0; it < 4; ++it) {
            int i4 = tid + it * 256;
            *(float4*)(Ss + (i4 >> 5) * 132 + (i4 & 31) * 4) = rs4[it];
        }
        __syncthreads();

        if (kt < 7) {
            #pragma unroll
            for (int it = 0; it < 16; ++it) {
                int idx = tid + it * 256;
                rq[it] = g_q[(rowbase + (idx >> 5)) * DD + (kt + 1) * 32 + (idx & 31)];
            }
            #pragma unroll
            for (int it = 0; it < 4; ++it) {
                int i4 = tid + it * 256;
                rs4[it] = *(const float4*)(Sbase + (size_t)((kt + 1) * 32 + (i4 >> 5)) * DD
                                           + nh * 128 + (i4 & 31) * 4);
            }
        }

        #pragma unroll
        for (int kk = 0; kk < 32; ++kk)
            MK_STEP(Qs + kk * 132 + ty * 8, Ss + kk * 132 + tx * 8);
    }

    #pragma unroll
    for (int i = 0; i < 8; ++i) {
        const int rr = ty * 8 + i;
        const float sc = powf(ALPHAF, (float)(rr + 1)) * 0.0625f;
        float o[8];
        up2(acc[i][0], o[0], o[1]); up2(acc[i][1], o[2], o[3]);
        up2(acc[i][2], o[4], o[5]); up2(acc[i][3], o[6], o[7]);
        float* op = out + (rowbase + rr) * DD + nh * 128 + tx * 8;
        float4 c0 = *(const float4*)op;
        float4 c1 = *(const float4*)(op + 4);
        *(float4*)op = make_float4(c0.x + sc * o[0], c0.y + sc * o[1],
                                   c0.z + sc * o[2], c0.w + sc * o[3]);
        *(float4*)(op + 4) = make_float4(c1.x + sc * o[4], c1.y + sc * o[5],
                                         c1.z + sc * o[6], c1.w + sc * o[7]);
    }
}

// ===========================================================================
extern "C" void kernel_launch(void* const* d_in, const int* in_sizes, int n_in,
                              void* d_out, int out_size) {
    const float* x    = (const float*)d_in[0];
    const float* W    = (const float*)d_in[1];
    const float* bias = (const float*)d_in[2];
    float* out = (float*)d_out;

    (void)in_sizes; (void)n_in; (void)out_size;

    cudaFuncSetAttribute(k_scores2, cudaFuncAttributeMaxDynamicSharedMemorySize,
                         SC2_SMEM);

    k_proj<<<dim3(MTOT / 128, NQKV / 128, 1), 256>>>(x, W, bias);
    k_scores2<<<BB * TT, 256, SC2_SMEM>>>(out);
    k_G<<<BB * TT * 4, 256>>>();
    k_prefix<<<512, 256>>>();
    k_inter<<<BB * TT * 2, 256>>>(out);
}